// round 16
// baseline (speedup 1.0000x reference)
#include <cuda_runtime.h>
#include <cuda_bf16.h>
#include <cstdint>

// ---------------------------------------------------------------------------
// Problem constants
// ---------------------------------------------------------------------------
#define BT    2048
#define H_S   1024
#define H_T   2048
#define VOCAB 32000
#define JSD_BETA 0.5f
#define IGNORE_INDEX (-100)

// GEMM tiling: 256 threads, 8 warps in a 2x4 grid, warp tile 64x32.
// Sized so TWO CTAs fit per SM (smem 99KB, regs <=128/thread) — the R13
// profile showed tensor=62.7% with occ=12.5%: single-CTA barrier bubbles.
#define BM 128
#define BN 128
#define BK 64                       // bf16 K per stage (128 bytes per row)
#define NTHREADS 256
#define A_STAGE_BYTES (BM * 128)    // 16 KB
#define B_STAGE_BYTES (BN * 128)    // 16 KB
#define STAGE_BYTES (A_STAGE_BYTES + B_STAGE_BYTES)  // 32 KB
#define NSTAGES 3
#define SMEM_REQ (1024 + NSTAGES * STAGE_BYTES)      // 99328; x2 = 198656 < 227KB

// Convert segmentation (in float4 quads)
#define NQ_S_IN  (BT * H_S / 4)
#define NQ_S_W   (VOCAB * H_S / 4)
#define NQ_T_IN  (BT * H_T / 4)
#define NQ_T_W   (VOCAB * H_T / 4)
#define NQ_TOTAL (NQ_S_IN + NQ_S_W + NQ_T_IN + NQ_T_W)

// ---------------------------------------------------------------------------
// Device scratch (static globals: allocation-free per harness rules)
// ---------------------------------------------------------------------------
__device__ __nv_bfloat16 g_s_in [BT * H_S];
__device__ __nv_bfloat16 g_t_in [BT * H_T];
__device__ __nv_bfloat16 g_s_w  [(size_t)VOCAB * H_S];
__device__ __nv_bfloat16 g_t_w  [(size_t)VOCAB * H_T];
__device__ __nv_bfloat16 g_s_logits[(size_t)BT * VOCAB];
__device__ __nv_bfloat16 g_t_logits[(size_t)BT * VOCAB];
__device__ float  g_rowsum_s[BT];
__device__ float  g_rowsum_t[BT];
__device__ double g_loss;

// ---------------------------------------------------------------------------
// PTX helpers (sm_80/sm_90 base instructions only — legal on generic sm_103)
// ---------------------------------------------------------------------------
__device__ __forceinline__ uint32_t smem_to_u32(const void* p) {
    uint32_t a;
    asm("{ .reg .u64 t; cvta.to.shared.u64 t, %1; cvt.u32.u64 %0, t; }"
        : "=r"(a) : "l"(p));
    return a;
}

__device__ __forceinline__ void cp_async16(uint32_t saddr, const void* gptr) {
    asm volatile("cp.async.cg.shared.global [%0], [%1], 16;"
                 :: "r"(saddr), "l"(gptr) : "memory");
}
__device__ __forceinline__ void cp_commit() {
    asm volatile("cp.async.commit_group;" ::: "memory");
}
template <int N>
__device__ __forceinline__ void cp_wait() {
    asm volatile("cp.async.wait_group %0;" :: "n"(N) : "memory");
}

__device__ __forceinline__ void ldmatrix_x4(uint32_t* r, uint32_t saddr) {
    asm volatile("ldmatrix.sync.aligned.m8n8.x4.shared.b16 {%0,%1,%2,%3}, [%4];"
                 : "=r"(r[0]), "=r"(r[1]), "=r"(r[2]), "=r"(r[3]) : "r"(saddr));
}

__device__ __forceinline__ void mma_16816(float* c, const uint32_t* a,
                                          uint32_t b0, uint32_t b1) {
    asm volatile(
        "mma.sync.aligned.m16n8k16.row.col.f32.bf16.bf16.f32 "
        "{%0,%1,%2,%3}, {%4,%5,%6,%7}, {%8,%9}, {%0,%1,%2,%3};"
        : "+f"(c[0]), "+f"(c[1]), "+f"(c[2]), "+f"(c[3])
        : "r"(a[0]), "r"(a[1]), "r"(a[2]), "r"(a[3]), "r"(b0), "r"(b1));
}

// Swizzled smem offset for a [rows][128B] tile: row*128 + (byte ^ ((row&7)<<4))
__device__ __forceinline__ uint32_t swz(uint32_t row, uint32_t byte) {
    return (row << 7) + (byte ^ ((row & 7u) << 4));
}

// ---------------------------------------------------------------------------
// Kernel 0: zero accumulators
// ---------------------------------------------------------------------------
__global__ void init_kernel() {
    int i = blockIdx.x * blockDim.x + threadIdx.x;
    if (i < BT) { g_rowsum_s[i] = 0.f; g_rowsum_t[i] = 0.f; }
    if (i == 0) g_loss = 0.0;
}

// ---------------------------------------------------------------------------
// Kernel 1: single fused f32 -> bf16 conversion of ALL four arrays.
// ---------------------------------------------------------------------------
__global__ __launch_bounds__(256)
void convert_all_kernel(const float* __restrict__ s_in, const float* __restrict__ s_w,
                        const float* __restrict__ t_in, const float* __restrict__ t_w) {
    int i = blockIdx.x * blockDim.x + threadIdx.x;
    if (i >= NQ_TOTAL) return;

    const float* src;
    __nv_bfloat16* dst;
    int off;
    if (i < NQ_S_IN) {
        src = s_in; dst = g_s_in; off = i;
    } else if (i < NQ_S_IN + NQ_S_W) {
        src = s_w;  dst = g_s_w;  off = i - NQ_S_IN;
    } else if (i < NQ_S_IN + NQ_S_W + NQ_T_IN) {
        src = t_in; dst = g_t_in; off = i - (NQ_S_IN + NQ_S_W);
    } else {
        src = t_w;  dst = g_t_w;  off = i - (NQ_S_IN + NQ_S_W + NQ_T_IN);
    }

    float4 v = ((const float4*)src)[off];
    __nv_bfloat162 lo = __floats2bfloat162_rn(v.x, v.y);
    __nv_bfloat162 hi = __floats2bfloat162_rn(v.z, v.w);
    uint2 o;
    o.x = *(uint32_t*)&lo;
    o.y = *(uint32_t*)&hi;
    ((uint2*)dst)[off] = o;
}

// ---------------------------------------------------------------------------
// Kernel 2: bf16 GEMM  logits = IN @ W^T  via mma.sync.m16n8k16.
// 8 warps (2x4), warp tile 64x32, cp.async 3-stage pipeline, 2 CTAs/SM,
// fused epilogue (bf16 logits + row exp-sums).
// which==0: student (K=1024), which==1: teacher (K=2048)
// ---------------------------------------------------------------------------
__global__ __launch_bounds__(NTHREADS, 2)
void gemm_kernel(int which) {
    extern __shared__ char smem_raw[];
    const __nv_bfloat16* A;
    const __nv_bfloat16* B;
    __nv_bfloat16* O;
    float* rowsum;
    int K;
    if (which == 0) { A = g_s_in; B = g_s_w; O = g_s_logits; rowsum = g_rowsum_s; K = H_S; }
    else            { A = g_t_in; B = g_t_w; O = g_t_logits; rowsum = g_rowsum_t; K = H_T; }
    const int NKC = K >> 6;   // K chunks of 64

    const int tid  = threadIdx.x;
    const int wid  = tid >> 5;
    const int lane = tid & 31;
    const int wm   = wid >> 2;        // 0..1 -> 64-row slab
    const int wn   = wid & 3;         // 0..3 -> 32-col slab
    const int m0   = (blockIdx.x & 15) * BM;     // m fast -> B tile reuse in L2
    const int n0   = (blockIdx.x >> 4) * BN;

    // 1024-align working smem
    uint32_t sb_raw = smem_to_u32(smem_raw);
    uint32_t sbase  = (sb_raw + 1023u) & ~1023u;
    char*    smemA  = smem_raw + (sbase - sb_raw);

    // ---- cp.async pattern: 8 x 16B segments per thread per stage.
    // j=0..3 -> A rows (tid/8 + j*32), j=0..3 -> B rows likewise.
    const int segR = tid >> 3;                 // 0..31
    const int segC = tid & 7;                  // 0..7
    const __nv_bfloat16* aG = A + (size_t)(m0 + segR) * K + segC * 8;
    const __nv_bfloat16* bG = B + (size_t)(n0 + segR) * K + segC * 8;
    const uint32_t aO = swz(segR, segC * 16);              // + j*32*128
    const uint32_t bO = A_STAGE_BYTES + aO;

    // ---- ldmatrix lane address components
    const int i4 = lane >> 3;                          // matrix index 0..3
    const int aRow   = wm * 64 + ((i4 & 1) << 3) + (lane & 7);   // + mf*16
    const int aByte  = (i4 >> 1) << 4;                           // + ks*32
    const uint32_t aSw = (aRow & 7) << 4;
    const int bRow   = wn * 32 + ((i4 >> 1) << 3) + (lane & 7);  // + q*16
    const int bByte  = (i4 & 1) << 4;                            // + ks*32
    const uint32_t bSw = (bRow & 7) << 4;

    float c[4][4][4];
    #pragma unroll
    for (int mf = 0; mf < 4; mf++)
        #pragma unroll
        for (int nf = 0; nf < 4; nf++)
            #pragma unroll
            for (int t = 0; t < 4; t++) c[mf][nf][t] = 0.f;

    // ---- prologue: fill NSTAGES-1 stages
    #pragma unroll
    for (int st = 0; st < NSTAGES - 1; st++) {
        uint32_t sb = sbase + st * STAGE_BYTES;
        const int koff = st * BK;
        #pragma unroll
        for (int j = 0; j < 4; j++)
            cp_async16(sb + aO + j * (32 * 128), aG + (size_t)j * 32 * K + koff);
        #pragma unroll
        for (int j = 0; j < 4; j++)
            cp_async16(sb + bO + j * (32 * 128), bG + (size_t)j * 32 * K + koff);
        cp_commit();
    }

    // ---- main loop
    for (int kc = 0; kc < NKC; kc++) {
        if (kc + NSTAGES - 1 < NKC) cp_wait<NSTAGES - 2>();
        else                        cp_wait<0>();
        __syncthreads();

        if (kc + NSTAGES - 1 < NKC) {
            uint32_t sb = sbase + ((kc + NSTAGES - 1) % NSTAGES) * STAGE_BYTES;
            const int koff = (kc + NSTAGES - 1) * BK;
            #pragma unroll
            for (int j = 0; j < 4; j++)
                cp_async16(sb + aO + j * (32 * 128), aG + (size_t)j * 32 * K + koff);
            #pragma unroll
            for (int j = 0; j < 4; j++)
                cp_async16(sb + bO + j * (32 * 128), bG + (size_t)j * 32 * K + koff);
            cp_commit();
        }

        const uint32_t aS = sbase + (kc % NSTAGES) * STAGE_BYTES;
        const uint32_t bS = aS + A_STAGE_BYTES;

        #pragma unroll
        for (int ks = 0; ks < 4; ks++) {
            uint32_t a[4][4];
            #pragma unroll
            for (int mf = 0; mf < 4; mf++)
                ldmatrix_x4(a[mf], aS + ((aRow + mf * 16) << 7) +
                                   (((uint32_t)(aByte | (ks << 5))) ^ aSw));
            uint32_t b[2][4];
            #pragma unroll
            for (int q = 0; q < 2; q++)
                ldmatrix_x4(b[q], bS + ((bRow + q * 16) << 7) +
                                  (((uint32_t)(bByte | (ks << 5))) ^ bSw));
            #pragma unroll
            for (int mf = 0; mf < 4; mf++)
                #pragma unroll
                for (int nf = 0; nf < 4; nf++)
                    mma_16816(c[mf][nf], a[mf],
                              b[nf >> 1][(nf & 1) * 2], b[nf >> 1][(nf & 1) * 2 + 1]);
        }
    }

    // ---- epilogue: bf16 logits + per-row sum(exp)
    __syncthreads();                       // pipeline smem dead; reuse for rowsums
    float* rs = (float*)smemA;
    if (tid < BM) rs[tid] = 0.f;
    __syncthreads();

    const int rloc = wm * 64 + (lane >> 2);           // + mf*16 (and +8)
    const int colb = n0 + wn * 32 + (lane & 3) * 2;   // + nf*8
    #pragma unroll
    for (int mf = 0; mf < 4; mf++) {
        float accLo = 0.f, accHi = 0.f;
        const int rowLo = m0 + rloc + mf * 16;
        __nv_bfloat16* oLo = O + (size_t)rowLo * VOCAB + colb;
        __nv_bfloat16* oHi = oLo + (size_t)8 * VOCAB;
        #pragma unroll
        for (int nf = 0; nf < 4; nf++) {
            __nv_bfloat162 lo = __floats2bfloat162_rn(c[mf][nf][0], c[mf][nf][1]);
            __nv_bfloat162 hi = __floats2bfloat162_rn(c[mf][nf][2], c[mf][nf][3]);
            *(__nv_bfloat162*)(oLo + nf * 8) = lo;
            *(__nv_bfloat162*)(oHi + nf * 8) = hi;
            accLo += __expf(__bfloat162float(lo.x)) + __expf(__bfloat162float(lo.y));
            accHi += __expf(__bfloat162float(hi.x)) + __expf(__bfloat162float(hi.y));
        }
        atomicAdd(&rs[rloc + mf * 16], accLo);
        atomicAdd(&rs[rloc + mf * 16 + 8], accHi);
    }
    __syncthreads();
    if (tid < BM) atomicAdd(&rowsum[m0 + tid], rs[tid]);
}

// ---------------------------------------------------------------------------
// Kernel 3: JSD reduction (lse folded in). One block per token row.
// ---------------------------------------------------------------------------
__global__ __launch_bounds__(256) void jsd_kernel(const int* __restrict__ label) {
    const int row = blockIdx.x;
    __shared__ float red[256];
    float acc = 0.f;
    if (label[row] != IGNORE_INDEX) {
        const float lse_s = __logf(g_rowsum_s[row]);
        const float lse_t = __logf(g_rowsum_t[row]);
        const uint4* ps4 = (const uint4*)(g_s_logits + (size_t)row * VOCAB);
        const uint4* pt4 = (const uint4*)(g_t_logits + (size_t)row * VOCAB);
        for (int c = threadIdx.x; c < VOCAB / 8; c += 256) {
            uint4 sv = ps4[c];
            uint4 tv = pt4[c];
            const uint32_t* su = &sv.x;
            const uint32_t* tu = &tv.x;
            #pragma unroll
            for (int w = 0; w < 4; w++) {
                float2 s2 = __bfloat1622float2(*(const __nv_bfloat162*)&su[w]);
                float2 t2 = __bfloat1622float2(*(const __nv_bfloat162*)&tu[w]);
                {
                    float ls = s2.x - lse_s, lt = t2.x - lse_t;
                    float q = __expf(ls), p = __expf(lt);
                    float logm = __logf(0.5f * (p + q));
                    acc += JSD_BETA * p * (lt - logm) + (1.f - JSD_BETA) * q * (ls - logm);
                }
                {
                    float ls = s2.y - lse_s, lt = t2.y - lse_t;
                    float q = __expf(ls), p = __expf(lt);
                    float logm = __logf(0.5f * (p + q));
                    acc += JSD_BETA * p * (lt - logm) + (1.f - JSD_BETA) * q * (ls - logm);
                }
            }
        }
    }
    red[threadIdx.x] = acc;
    __syncthreads();
    for (int s = 128; s > 0; s >>= 1) {
        if (threadIdx.x < s) red[threadIdx.x] += red[threadIdx.x + s];
        __syncthreads();
    }
    if (threadIdx.x == 0) atomicAdd(&g_loss, (double)red[0]);
}

// ---------------------------------------------------------------------------
// Kernel 4: finalize loss = sum / n_non_ignore
// ---------------------------------------------------------------------------
__global__ void finalize_kernel(const int* __restrict__ label, float* __restrict__ out) {
    __shared__ int red[256];
    int c = 0;
    for (int i = threadIdx.x; i < BT; i += 256) c += (label[i] != IGNORE_INDEX);
    red[threadIdx.x] = c;
    __syncthreads();
    for (int s = 128; s > 0; s >>= 1) {
        if (threadIdx.x < s) red[threadIdx.x] += red[threadIdx.x + s];
        __syncthreads();
    }
    if (threadIdx.x == 0) {
        int n = red[0] > 1 ? red[0] : 1;
        out[0] = (float)(g_loss / (double)n);
    }
}

// ---------------------------------------------------------------------------
// Launch.  Order keeps the teacher GEMM in ncu's fixed capture slot.
// ---------------------------------------------------------------------------
extern "C" void kernel_launch(void* const* d_in, const int* in_sizes, int n_in,
                              void* d_out, int out_size) {
    const float* s_in = (const float*)d_in[0];
    const float* s_w  = (const float*)d_in[1];
    const float* t_in = (const float*)d_in[2];
    const float* t_w  = (const float*)d_in[3];
    const int*   lab  = (const int*)d_in[4];
    float* out = (float*)d_out;

    cudaFuncSetAttribute(gemm_kernel, cudaFuncAttributeMaxDynamicSharedMemorySize, SMEM_REQ);

    convert_all_kernel<<<(NQ_TOTAL + 255) / 256, 256>>>(s_in, s_w, t_in, t_w);
    init_kernel<<<(BT + 255) / 256, 256>>>();

    const int grid = (BT / BM) * (VOCAB / BN);  // 16 * 250 = 4000
    gemm_kernel<<<grid, NTHREADS, SMEM_REQ>>>(0);
    gemm_kernel<<<grid, NTHREADS, SMEM_REQ>>>(1);

    jsd_kernel<<<BT, 256>>>(lab);
    finalize_kernel<<<1, 256>>>(lab, out);
}

// round 17
// speedup vs baseline: 1.4872x; 1.4872x over previous
#include <cuda_runtime.h>
#include <cuda_bf16.h>
#include <cstdint>

// ---------------------------------------------------------------------------
// Problem constants
// ---------------------------------------------------------------------------
#define BT    2048
#define H_S   1024
#define H_T   2048
#define VOCAB 32000
#define JSD_BETA 0.5f
#define IGNORE_INDEX (-100)

// GEMM tiling: 256 threads, 8 warps in a 2x4 grid, warp tile 64x64 (champion),
// but pipelined as 2 mega-stages x 128-K each (2 x 48KB sub-chunks per stage)
// to HALVE the per-K barrier frequency (R13: tensor=62.7%, idle = barriers).
#define BM 128
#define BN 256
#define BK 64                        // bf16 K per sub-chunk (128 bytes per row)
#define NTHREADS 256
#define A_SUB_BYTES (BM * 128)       // 16 KB
#define B_SUB_BYTES (BN * 128)       // 32 KB
#define SUB_BYTES (A_SUB_BYTES + B_SUB_BYTES)   // 48 KB
#define STAGE_BYTES (2 * SUB_BYTES)  // 96 KB = 128-K mega-stage
#define NSTAGES 2
#define SMEM_REQ (1024 + NSTAGES * STAGE_BYTES) // 197632 < 227KB

// Convert segmentation (in float4 quads)
#define NQ_S_IN  (BT * H_S / 4)
#define NQ_S_W   (VOCAB * H_S / 4)
#define NQ_T_IN  (BT * H_T / 4)
#define NQ_T_W   (VOCAB * H_T / 4)
#define NQ_TOTAL (NQ_S_IN + NQ_S_W + NQ_T_IN + NQ_T_W)

// ---------------------------------------------------------------------------
// Device scratch (static globals: allocation-free per harness rules)
// ---------------------------------------------------------------------------
__device__ __nv_bfloat16 g_s_in [BT * H_S];
__device__ __nv_bfloat16 g_t_in [BT * H_T];
__device__ __nv_bfloat16 g_s_w  [(size_t)VOCAB * H_S];
__device__ __nv_bfloat16 g_t_w  [(size_t)VOCAB * H_T];
__device__ __nv_bfloat16 g_s_logits[(size_t)BT * VOCAB];
__device__ __nv_bfloat16 g_t_logits[(size_t)BT * VOCAB];
__device__ float  g_rowsum_s[BT];
__device__ float  g_rowsum_t[BT];
__device__ double g_loss;

// ---------------------------------------------------------------------------
// PTX helpers (sm_80/sm_90 base instructions only — legal on generic sm_103)
// ---------------------------------------------------------------------------
__device__ __forceinline__ uint32_t smem_to_u32(const void* p) {
    uint32_t a;
    asm("{ .reg .u64 t; cvta.to.shared.u64 t, %1; cvt.u32.u64 %0, t; }"
        : "=r"(a) : "l"(p));
    return a;
}

__device__ __forceinline__ void cp_async16(uint32_t saddr, const void* gptr) {
    asm volatile("cp.async.cg.shared.global [%0], [%1], 16;"
                 :: "r"(saddr), "l"(gptr) : "memory");
}
__device__ __forceinline__ void cp_commit() {
    asm volatile("cp.async.commit_group;" ::: "memory");
}
template <int N>
__device__ __forceinline__ void cp_wait() {
    asm volatile("cp.async.wait_group %0;" :: "n"(N) : "memory");
}

__device__ __forceinline__ void ldmatrix_x4(uint32_t* r, uint32_t saddr) {
    asm volatile("ldmatrix.sync.aligned.m8n8.x4.shared.b16 {%0,%1,%2,%3}, [%4];"
                 : "=r"(r[0]), "=r"(r[1]), "=r"(r[2]), "=r"(r[3]) : "r"(saddr));
}

__device__ __forceinline__ void mma_16816(float* c, const uint32_t* a,
                                          uint32_t b0, uint32_t b1) {
    asm volatile(
        "mma.sync.aligned.m16n8k16.row.col.f32.bf16.bf16.f32 "
        "{%0,%1,%2,%3}, {%4,%5,%6,%7}, {%8,%9}, {%0,%1,%2,%3};"
        : "+f"(c[0]), "+f"(c[1]), "+f"(c[2]), "+f"(c[3])
        : "r"(a[0]), "r"(a[1]), "r"(a[2]), "r"(a[3]), "r"(b0), "r"(b1));
}

// Swizzled smem offset for a [rows][128B] tile: row*128 + (byte ^ ((row&7)<<4))
__device__ __forceinline__ uint32_t swz(uint32_t row, uint32_t byte) {
    return (row << 7) + (byte ^ ((row & 7u) << 4));
}

// ---------------------------------------------------------------------------
// Kernel 0: zero accumulators
// ---------------------------------------------------------------------------
__global__ void init_kernel() {
    int i = blockIdx.x * blockDim.x + threadIdx.x;
    if (i < BT) { g_rowsum_s[i] = 0.f; g_rowsum_t[i] = 0.f; }
    if (i == 0) g_loss = 0.0;
}

// ---------------------------------------------------------------------------
// Kernel 1: single fused f32 -> bf16 conversion of ALL four arrays.
// ---------------------------------------------------------------------------
__global__ __launch_bounds__(256)
void convert_all_kernel(const float* __restrict__ s_in, const float* __restrict__ s_w,
                        const float* __restrict__ t_in, const float* __restrict__ t_w) {
    int i = blockIdx.x * blockDim.x + threadIdx.x;
    if (i >= NQ_TOTAL) return;

    const float* src;
    __nv_bfloat16* dst;
    int off;
    if (i < NQ_S_IN) {
        src = s_in; dst = g_s_in; off = i;
    } else if (i < NQ_S_IN + NQ_S_W) {
        src = s_w;  dst = g_s_w;  off = i - NQ_S_IN;
    } else if (i < NQ_S_IN + NQ_S_W + NQ_T_IN) {
        src = t_in; dst = g_t_in; off = i - (NQ_S_IN + NQ_S_W);
    } else {
        src = t_w;  dst = g_t_w;  off = i - (NQ_S_IN + NQ_S_W + NQ_T_IN);
    }

    float4 v = ((const float4*)src)[off];
    __nv_bfloat162 lo = __floats2bfloat162_rn(v.x, v.y);
    __nv_bfloat162 hi = __floats2bfloat162_rn(v.z, v.w);
    uint2 o;
    o.x = *(uint32_t*)&lo;
    o.y = *(uint32_t*)&hi;
    ((uint2*)dst)[off] = o;
}

// ---------------------------------------------------------------------------
// Kernel 2: bf16 GEMM  logits = IN @ W^T  via mma.sync.m16n8k16.
// 8 warps (2x4), warp tile 64x64, 2 mega-stage (128-K) cp.async pipeline,
// fused epilogue (bf16 logits + row exp-sums).
// which==0: student (K=1024), which==1: teacher (K=2048)
// ---------------------------------------------------------------------------
__global__ __launch_bounds__(NTHREADS, 1)
void gemm_kernel(int which) {
    extern __shared__ char smem_raw[];
    const __nv_bfloat16* A;
    const __nv_bfloat16* B;
    __nv_bfloat16* O;
    float* rowsum;
    int K;
    if (which == 0) { A = g_s_in; B = g_s_w; O = g_s_logits; rowsum = g_rowsum_s; K = H_S; }
    else            { A = g_t_in; B = g_t_w; O = g_t_logits; rowsum = g_rowsum_t; K = H_T; }
    const int NBC = K >> 7;   // mega-chunks of 128 K

    const int tid  = threadIdx.x;
    const int wid  = tid >> 5;
    const int lane = tid & 31;
    const int wm   = wid >> 2;        // 0..1 -> 64-row slab
    const int wn   = wid & 3;         // 0..3 -> 64-col slab
    const int m0   = (blockIdx.x & 15) * BM;     // m fast -> B tile reuse in L2
    const int n0   = (blockIdx.x >> 4) * BN;

    // 1024-align working smem
    uint32_t sb_raw = smem_to_u32(smem_raw);
    uint32_t sbase  = (sb_raw + 1023u) & ~1023u;
    char*    smemA  = smem_raw + (sbase - sb_raw);

    // ---- cp.async pattern: per 48KB sub-chunk, 12 x 16B segs per thread.
    const int segR = tid >> 3;                 // 0..31
    const int segC = tid & 7;                  // 0..7
    const __nv_bfloat16* aG = A + (size_t)(m0 + segR) * K + segC * 8;
    const __nv_bfloat16* bG = B + (size_t)(n0 + segR) * K + segC * 8;
    const uint32_t aO = swz(segR, segC * 16);              // + j*32*128
    const uint32_t bO = A_SUB_BYTES + aO;

    // ---- ldmatrix lane address components
    const int i4 = lane >> 3;                          // matrix index 0..3
    const int aRow   = wm * 64 + ((i4 & 1) << 3) + (lane & 7);   // + mf*16
    const int aByte  = (i4 >> 1) << 4;                           // + ks*32
    const uint32_t aSw = (aRow & 7) << 4;
    const int bRow   = wn * 64 + ((i4 >> 1) << 3) + (lane & 7);  // + q*16
    const int bByte  = (i4 & 1) << 4;                            // + ks*32
    const uint32_t bSw = (bRow & 7) << 4;

    float c[4][8][4];
    #pragma unroll
    for (int mf = 0; mf < 4; mf++)
        #pragma unroll
        for (int nf = 0; nf < 8; nf++)
            #pragma unroll
            for (int t = 0; t < 4; t++) c[mf][nf][t] = 0.f;

    // ---- prologue: fill mega-stage 0 (both 64-K sub-chunks), one group
    #pragma unroll
    for (int sub = 0; sub < 2; sub++) {
        uint32_t sb = sbase + sub * SUB_BYTES;
        const int koff = sub * BK;
        #pragma unroll
        for (int j = 0; j < 4; j++)
            cp_async16(sb + aO + j * (32 * 128), aG + (size_t)j * 32 * K + koff);
        #pragma unroll
        for (int j = 0; j < 8; j++)
            cp_async16(sb + bO + j * (32 * 128), bG + (size_t)j * 32 * K + koff);
    }
    cp_commit();

    // ---- main loop over 128-K mega-chunks
    for (int bc = 0; bc < NBC; bc++) {
        cp_wait<0>();          // mega-stage bc fill complete (issued 1 iter ago)
        __syncthreads();       // publish to all warps; all done reading buf bc^1

        // Prefetch mega-stage bc+1 into the other buffer. Safe: that buffer
        // was last read in iteration bc-1, and every warp has passed the
        // barrier above before these writes are issued.
        if (bc + 1 < NBC) {
            uint32_t sbb = sbase + ((bc + 1) & 1) * STAGE_BYTES;
            const int kbase = (bc + 1) * 128;
            #pragma unroll
            for (int sub = 0; sub < 2; sub++) {
                uint32_t sb = sbb + sub * SUB_BYTES;
                const int koff = kbase + sub * BK;
                #pragma unroll
                for (int j = 0; j < 4; j++)
                    cp_async16(sb + aO + j * (32 * 128), aG + (size_t)j * 32 * K + koff);
                #pragma unroll
                for (int j = 0; j < 8; j++)
                    cp_async16(sb + bO + j * (32 * 128), bG + (size_t)j * 32 * K + koff);
            }
            cp_commit();
        }

        // Compute both 64-K sub-chunks of mega-stage bc
        #pragma unroll
        for (int sub = 0; sub < 2; sub++) {
            const uint32_t aS = sbase + (bc & 1) * STAGE_BYTES + sub * SUB_BYTES;
            const uint32_t bS = aS + A_SUB_BYTES;

            #pragma unroll
            for (int ks = 0; ks < 4; ks++) {
                uint32_t a[4][4];
                #pragma unroll
                for (int mf = 0; mf < 4; mf++)
                    ldmatrix_x4(a[mf], aS + ((aRow + mf * 16) << 7) +
                                       (((uint32_t)(aByte | (ks << 5))) ^ aSw));
                uint32_t b[4][4];
                #pragma unroll
                for (int q = 0; q < 4; q++)
                    ldmatrix_x4(b[q], bS + ((bRow + q * 16) << 7) +
                                      (((uint32_t)(bByte | (ks << 5))) ^ bSw));
                #pragma unroll
                for (int mf = 0; mf < 4; mf++)
                    #pragma unroll
                    for (int nf = 0; nf < 8; nf++)
                        mma_16816(c[mf][nf], a[mf],
                                  b[nf >> 1][(nf & 1) * 2], b[nf >> 1][(nf & 1) * 2 + 1]);
            }
        }
    }

    // ---- epilogue: bf16 logits + per-row sum(exp)
    __syncthreads();                       // pipeline smem dead; reuse for rowsums
    float* rs = (float*)smemA;
    if (tid < BM) rs[tid] = 0.f;
    __syncthreads();

    const int rloc = wm * 64 + (lane >> 2);           // + mf*16 (and +8)
    const int colb = n0 + wn * 64 + (lane & 3) * 2;   // + nf*8
    #pragma unroll
    for (int mf = 0; mf < 4; mf++) {
        float accLo = 0.f, accHi = 0.f;
        const int rowLo = m0 + rloc + mf * 16;
        __nv_bfloat16* oLo = O + (size_t)rowLo * VOCAB + colb;
        __nv_bfloat16* oHi = oLo + (size_t)8 * VOCAB;
        #pragma unroll
        for (int nf = 0; nf < 8; nf++) {
            __nv_bfloat162 lo = __floats2bfloat162_rn(c[mf][nf][0], c[mf][nf][1]);
            __nv_bfloat162 hi = __floats2bfloat162_rn(c[mf][nf][2], c[mf][nf][3]);
            *(__nv_bfloat162*)(oLo + nf * 8) = lo;
            *(__nv_bfloat162*)(oHi + nf * 8) = hi;
            accLo += __expf(__bfloat162float(lo.x)) + __expf(__bfloat162float(lo.y));
            accHi += __expf(__bfloat162float(hi.x)) + __expf(__bfloat162float(hi.y));
        }
        atomicAdd(&rs[rloc + mf * 16], accLo);
        atomicAdd(&rs[rloc + mf * 16 + 8], accHi);
    }
    __syncthreads();
    if (tid < BM) atomicAdd(&rowsum[m0 + tid], rs[tid]);
}

// ---------------------------------------------------------------------------
// Kernel 3: JSD reduction (lse folded in). One block per token row.
// ---------------------------------------------------------------------------
__global__ __launch_bounds__(256) void jsd_kernel(const int* __restrict__ label) {
    const int row = blockIdx.x;
    __shared__ float red[256];
    float acc = 0.f;
    if (label[row] != IGNORE_INDEX) {
        const float lse_s = __logf(g_rowsum_s[row]);
        const float lse_t = __logf(g_rowsum_t[row]);
        const uint4* ps4 = (const uint4*)(g_s_logits + (size_t)row * VOCAB);
        const uint4* pt4 = (const uint4*)(g_t_logits + (size_t)row * VOCAB);
        for (int c = threadIdx.x; c < VOCAB / 8; c += 256) {
            uint4 sv = ps4[c];
            uint4 tv = pt4[c];
            const uint32_t* su = &sv.x;
            const uint32_t* tu = &tv.x;
            #pragma unroll
            for (int w = 0; w < 4; w++) {
                float2 s2 = __bfloat1622float2(*(const __nv_bfloat162*)&su[w]);
                float2 t2 = __bfloat1622float2(*(const __nv_bfloat162*)&tu[w]);
                {
                    float ls = s2.x - lse_s, lt = t2.x - lse_t;
                    float q = __expf(ls), p = __expf(lt);
                    float logm = __logf(0.5f * (p + q));
                    acc += JSD_BETA * p * (lt - logm) + (1.f - JSD_BETA) * q * (ls - logm);
                }
                {
                    float ls = s2.y - lse_s, lt = t2.y - lse_t;
                    float q = __expf(ls), p = __expf(lt);
                    float logm = __logf(0.5f * (p + q));
                    acc += JSD_BETA * p * (lt - logm) + (1.f - JSD_BETA) * q * (ls - logm);
                }
            }
        }
    }
    red[threadIdx.x] = acc;
    __syncthreads();
    for (int s = 128; s > 0; s >>= 1) {
        if (threadIdx.x < s) red[threadIdx.x] += red[threadIdx.x + s];
        __syncthreads();
    }
    if (threadIdx.x == 0) atomicAdd(&g_loss, (double)red[0]);
}

// ---------------------------------------------------------------------------
// Kernel 4: finalize loss = sum / n_non_ignore
// ---------------------------------------------------------------------------
__global__ void finalize_kernel(const int* __restrict__ label, float* __restrict__ out) {
    __shared__ int red[256];
    int c = 0;
    for (int i = threadIdx.x; i < BT; i += 256) c += (label[i] != IGNORE_INDEX);
    red[threadIdx.x] = c;
    __syncthreads();
    for (int s = 128; s > 0; s >>= 1) {
        if (threadIdx.x < s) red[threadIdx.x] += red[threadIdx.x + s];
        __syncthreads();
    }
    if (threadIdx.x == 0) {
        int n = red[0] > 1 ? red[0] : 1;
        out[0] = (float)(g_loss / (double)n);
    }
}

// ---------------------------------------------------------------------------
// Launch.  Order keeps the teacher GEMM in ncu's fixed capture slot.
// ---------------------------------------------------------------------------
extern "C" void kernel_launch(void* const* d_in, const int* in_sizes, int n_in,
                              void* d_out, int out_size) {
    const float* s_in = (const float*)d_in[0];
    const float* s_w  = (const float*)d_in[1];
    const float* t_in = (const float*)d_in[2];
    const float* t_w  = (const float*)d_in[3];
    const int*   lab  = (const int*)d_in[4];
    float* out = (float*)d_out;

    cudaFuncSetAttribute(gemm_kernel, cudaFuncAttributeMaxDynamicSharedMemorySize, SMEM_REQ);

    convert_all_kernel<<<(NQ_TOTAL + 255) / 256, 256>>>(s_in, s_w, t_in, t_w);
    init_kernel<<<(BT + 255) / 256, 256>>>();

    const int grid = (BT / BM) * (VOCAB / BN);  // 16 * 125 = 2000
    gemm_kernel<<<grid, NTHREADS, SMEM_REQ>>>(0);
    gemm_kernel<<<grid, NTHREADS, SMEM_REQ>>>(1);

    jsd_kernel<<<BT, 256>>>(lab);
    finalize_kernel<<<1, 256>>>(lab, out);
}